// round 11
// baseline (speedup 1.0000x reference)
#include <cuda_runtime.h>
#include <cuda_fp16.h>
#include <cstdint>
#include <cstddef>

// Problem sizes (fixed by the dataset)
static constexpr int TOKENS = 8192;
static constexpr int INDIM  = 4096;
static constexpr int OUTDIM = 4096;
static constexpr int GROUPS = 32;      // INDIM / 128

// fp16 staging buffers (static device allocs are allowed; cudaMalloc is not)
__device__ __half g_Xh[(size_t)TOKENS * INDIM];   // 64 MB
__device__ __half g_Wh[(size_t)OUTDIM * INDIM];   // 32 MB

// ---------------------------------------------------------------------------
// Fused prologue: blocks [0, XBLK) convert x -> fp16; the rest dequantize W.
// ---------------------------------------------------------------------------
static constexpr int XBLK = (TOKENS * (INDIM / 4)) / 256;    // 32768
static constexpr int WBLK = (OUTDIM * (INDIM / 4)) / 256;    // 16384

__global__ void __launch_bounds__(256)
prep_kernel(const float* __restrict__ x, const int* __restrict__ Q,
            const float* __restrict__ scales) {
    if (blockIdx.x < XBLK) {
        size_t i = (size_t)blockIdx.x * 256 + threadIdx.x;     // float4 index
        float4 v = reinterpret_cast<const float4*>(x)[i];
        __half2 h0 = __floats2half2_rn(v.x, v.y);
        __half2 h1 = __floats2half2_rn(v.z, v.w);
        uint2 u;
        u.x = *reinterpret_cast<uint32_t*>(&h0);
        u.y = *reinterpret_cast<uint32_t*>(&h1);
        reinterpret_cast<uint2*>(g_Xh)[i] = u;
    } else {
        size_t i = (size_t)(blockIdx.x - XBLK) * 256 + threadIdx.x;  // int4 idx
        int4 q = reinterpret_cast<const int4*>(Q)[i];
        size_t lin = i * 4;
        int o = (int)(lin >> 12);            // / 4096
        int k = (int)(lin & 4095);
        float s = __ldg(scales + o * GROUPS + (k >> 7));
        __half2 h0 = __floats2half2_rn((float)q.x * s, (float)q.y * s);
        __half2 h1 = __floats2half2_rn((float)q.z * s, (float)q.w * s);
        uint2 u;
        u.x = *reinterpret_cast<uint32_t*>(&h0);
        u.y = *reinterpret_cast<uint32_t*>(&h1);
        reinterpret_cast<uint2*>(g_Wh)[i] = u;
    }
}

// ---------------------------------------------------------------------------
// Helpers
// ---------------------------------------------------------------------------
__device__ __forceinline__ uint32_t smem_u32(const void* p) {
    uint32_t a;
    asm("{ .reg .u64 t; cvta.to.shared.u64 t, %1; cvt.u32.u64 %0, t; }"
        : "=r"(a) : "l"(p));
    return a;
}

__device__ __forceinline__ uint32_t sw128(uint32_t o) {
    return o ^ ((o >> 3) & 0x70);
}

__device__ __forceinline__ void ldsm_x4(uint32_t* r, uint32_t addr) {
    asm volatile("ldmatrix.sync.aligned.m8n8.x4.shared.b16 {%0,%1,%2,%3}, [%4];"
                 : "=r"(r[0]), "=r"(r[1]), "=r"(r[2]), "=r"(r[3])
                 : "r"(addr));
}

__device__ __forceinline__ void mma16816(float* c, const uint32_t* a,
                                         const uint32_t* b) {
    asm volatile(
        "mma.sync.aligned.m16n8k16.row.col.f32.f16.f16.f32 "
        "{%0,%1,%2,%3}, {%4,%5,%6,%7}, {%8,%9}, {%0,%1,%2,%3};"
        : "+f"(c[0]), "+f"(c[1]), "+f"(c[2]), "+f"(c[3])
        : "r"(a[0]), "r"(a[1]), "r"(a[2]), "r"(a[3]), "r"(b[0]), "r"(b[1]));
}

// ---------------------------------------------------------------------------
// GEMM: C[8192,4096] = Xh @ Wh^T + bias
// BM=128, BN=128, BK=64, 3 stages, 256 threads (8 warps, 2x4), warp tile
// 64x32, 2 CTAs/SM. Loader addresses algebraically precomputed; post-barrier
// order: ldsm(ks0) -> cp.async prefetch -> MMAs (shortens tensor-idle shadow).
// ---------------------------------------------------------------------------
static constexpr int BM = 128;
static constexpr int BN = 128;
static constexpr int BK = 64;                 // halves; 128 bytes per row
static constexpr int STAGES = 3;
static constexpr int KITERS = INDIM / BK;     // 64
static constexpr int A_BYTES = BM * 128;      // 16384
static constexpr int STAGE_BYTES = A_BYTES + BN * 128;  // 32768
static constexpr int SMEM_BYTES = STAGES * STAGE_BYTES + 1024;  // 99328

__global__ void __launch_bounds__(256, 2)
gemm_kernel(float* __restrict__ out, const float* __restrict__ bias) {
    extern __shared__ char smem[];
    const uint32_t sb = (smem_u32(smem) + 1023u) & ~1023u;
    const int tid  = threadIdx.x;
    const int lane = tid & 31;
    const int wid  = tid >> 5;
    const int wm   = wid >> 2;    // 0..1 (64 rows each)
    const int wn   = wid & 3;     // 0..3 (32 cols each)
    const int n0   = blockIdx.x * BN;
    const int m0   = blockIdx.y * BM;

    // --- Loader bases (j-invariant algebra):
    // chunk c = tid + j*256  ->  row = (tid>>3) + 32j, chunk-in-row = tid&7.
    // 32j = 0 mod 8  =>  swizzle XOR is j-invariant: soff(j) = soff0 + j*4096.
    const int base_r = tid >> 3;
    const uint32_t so0 = sw128((uint32_t)(base_r * 128 + (tid & 7) * 16));
    const __half* gA = g_Xh + (size_t)(m0 + base_r) * INDIM + (tid & 7) * 8;
    const __half* gB = g_Wh + (size_t)(n0 + base_r) * INDIM + (tid & 7) * 8;
    static constexpr size_t RSTRIDE = (size_t)32 * INDIM;   // 32 rows

    auto load_stage = [&](int s, int kiter) {
        const uint32_t st = sb + s * STAGE_BYTES;
        const int k0 = kiter * BK;
        #pragma unroll
        for (int j = 0; j < 4; j++)
            asm volatile("cp.async.cg.shared.global [%0], [%1], 16;"
                         :: "r"(st + so0 + j * 4096),
                            "l"(gA + j * RSTRIDE + k0) : "memory");
        #pragma unroll
        for (int j = 0; j < 4; j++)
            asm volatile("cp.async.cg.shared.global [%0], [%1], 16;"
                         :: "r"(st + A_BYTES + so0 + j * 4096),
                            "l"(gB + j * RSTRIDE + k0) : "memory");
        asm volatile("cp.async.commit_group;" ::: "memory");
    };

    // Per-thread ldmatrix address components
    const int a_row = lane & 15;                       // 0..15
    const int a_col = (lane >> 4) << 4;                // 0 or 16 bytes
    const uint32_t a_xor = (uint32_t)((a_row & 7) << 4);
    const int b_row = ((lane >> 4) << 3) | (lane & 7); // 0..15
    const int b_col = ((lane >> 3) & 1) << 4;          // 0 or 16 bytes
    const uint32_t b_xor = (uint32_t)((b_row & 7) << 4);

    float acc[4][4][4];   // [m16 tile][n8 tile][frag]
    #pragma unroll
    for (int mt = 0; mt < 4; mt++)
        #pragma unroll
        for (int n = 0; n < 4; n++)
            #pragma unroll
            for (int j = 0; j < 4; j++) acc[mt][n][j] = 0.0f;

    // Prologue: 2 stages in flight
    load_stage(0, 0);
    load_stage(1, 1);

    int s = 0;
    for (int i = 0; i < KITERS; i++) {
        asm volatile("cp.async.wait_group 1;" ::: "memory");
        __syncthreads();

        const uint32_t stg = sb + s * STAGE_BYTES;
        const uint32_t aT = stg + (uint32_t)((wm * 64 + a_row) * 128);
        const uint32_t bT = stg + A_BYTES + (uint32_t)((wn * 32 + b_row) * 128);

        // 1) ks=0 fragment loads first (latency covered by prefetch issue)
        uint32_t af[4][4], bf[2][4];
        #pragma unroll
        for (int mt = 0; mt < 4; mt++)
            ldsm_x4(af[mt], aT + (uint32_t)(mt * 16 * 128)
                               + (((uint32_t)a_col) ^ a_xor));
        #pragma unroll
        for (int nt = 0; nt < 2; nt++)
            ldsm_x4(bf[nt], bT + (uint32_t)(nt * 16 * 128)
                               + (((uint32_t)b_col) ^ b_xor));

        // 2) prefetch stage i+2 (freed by the barrier above)
        if (i + 2 < KITERS) {
            load_stage(s == 0 ? 2 : s - 1, i + 2);   // (i+2)%3
        } else {
            asm volatile("cp.async.commit_group;" ::: "memory");
        }

        // 3) ks=0 MMAs
        #pragma unroll
        for (int mt = 0; mt < 4; mt++)
            #pragma unroll
            for (int nt = 0; nt < 2; nt++) {
                mma16816(acc[mt][2 * nt],     af[mt], &bf[nt][0]);
                mma16816(acc[mt][2 * nt + 1], af[mt], &bf[nt][2]);
            }

        // 4) ks = 1..3
        #pragma unroll
        for (int ks = 1; ks < 4; ks++) {
            #pragma unroll
            for (int mt = 0; mt < 4; mt++)
                ldsm_x4(af[mt], aT + (uint32_t)(mt * 16 * 128)
                                   + (((uint32_t)(ks * 32 + a_col)) ^ a_xor));
            #pragma unroll
            for (int nt = 0; nt < 2; nt++)
                ldsm_x4(bf[nt], bT + (uint32_t)(nt * 16 * 128)
                                   + (((uint32_t)(ks * 32 + b_col)) ^ b_xor));
            #pragma unroll
            for (int mt = 0; mt < 4; mt++)
                #pragma unroll
                for (int nt = 0; nt < 2; nt++) {
                    mma16816(acc[mt][2 * nt],     af[mt], &bf[nt][0]);
                    mma16816(acc[mt][2 * nt + 1], af[mt], &bf[nt][2]);
                }
        }
        s = (s == STAGES - 1) ? 0 : s + 1;
    }

    // Epilogue: direct fp32 stores with bias
    const int qr = lane >> 2, qc = lane & 3;
    float bv[4][2];
    #pragma unroll
    for (int n = 0; n < 4; n++) {
        const int col = n0 + wn * 32 + n * 8 + qc * 2;
        bv[n][0] = __ldg(bias + col);
        bv[n][1] = __ldg(bias + col + 1);
    }
    #pragma unroll
    for (int mt = 0; mt < 4; mt++) {
        #pragma unroll
        for (int h = 0; h < 2; h++) {
            const int row = m0 + wm * 64 + mt * 16 + qr + h * 8;
            float* orow = out + (size_t)row * OUTDIM + n0 + wn * 32;
            #pragma unroll
            for (int n = 0; n < 4; n++) {
                float2 v;
                v.x = acc[mt][n][2 * h]     + bv[n][0];
                v.y = acc[mt][n][2 * h + 1] + bv[n][1];
                *reinterpret_cast<float2*>(orow + n * 8 + qc * 2) = v;
            }
        }
    }
}

// ---------------------------------------------------------------------------
// Harness entry
// ---------------------------------------------------------------------------
extern "C" void kernel_launch(void* const* d_in, const int* in_sizes, int n_in,
                              void* d_out, int out_size) {
    const float* x      = (const float*)d_in[0];
    const int*   Qw     = (const int*)d_in[1];
    const float* scales = (const float*)d_in[2];
    const float* bias   = (const float*)d_in[3];
    float*       out    = (float*)d_out;

    prep_kernel<<<XBLK + WBLK, 256>>>(x, Qw, scales);

    cudaFuncSetAttribute(gemm_kernel,
                         cudaFuncAttributeMaxDynamicSharedMemorySize, SMEM_BYTES);
    gemm_kernel<<<dim3(OUTDIM / BN, TOKENS / BM), 256, SMEM_BYTES>>>(out, bias);
}

// round 12
// speedup vs baseline: 1.0401x; 1.0401x over previous
#include <cuda_runtime.h>
#include <cuda_fp16.h>
#include <cstdint>
#include <cstddef>

// Problem sizes (fixed by the dataset)
static constexpr int TOKENS = 8192;
static constexpr int INDIM  = 4096;
static constexpr int OUTDIM = 4096;
static constexpr int GROUPS = 32;      // INDIM / 128

// fp16 staging buffers (static device allocs are allowed; cudaMalloc is not)
__device__ __half g_Xh[(size_t)TOKENS * INDIM];   // 64 MB
__device__ __half g_Wh[(size_t)OUTDIM * INDIM];   // 32 MB

// ---------------------------------------------------------------------------
// Fused prologue: blocks [0, XBLK) convert x -> fp16; the rest dequantize W.
// ---------------------------------------------------------------------------
static constexpr int XBLK = (TOKENS * (INDIM / 4)) / 256;    // 32768
static constexpr int WBLK = (OUTDIM * (INDIM / 4)) / 256;    // 16384

__global__ void __launch_bounds__(256)
prep_kernel(const float* __restrict__ x, const int* __restrict__ Q,
            const float* __restrict__ scales) {
    if (blockIdx.x < XBLK) {
        size_t i = (size_t)blockIdx.x * 256 + threadIdx.x;     // float4 index
        float4 v = reinterpret_cast<const float4*>(x)[i];
        __half2 h0 = __floats2half2_rn(v.x, v.y);
        __half2 h1 = __floats2half2_rn(v.z, v.w);
        uint2 u;
        u.x = *reinterpret_cast<uint32_t*>(&h0);
        u.y = *reinterpret_cast<uint32_t*>(&h1);
        reinterpret_cast<uint2*>(g_Xh)[i] = u;
    } else {
        size_t i = (size_t)(blockIdx.x - XBLK) * 256 + threadIdx.x;  // int4 idx
        int4 q = reinterpret_cast<const int4*>(Q)[i];
        size_t lin = i * 4;
        int o = (int)(lin >> 12);            // / 4096
        int k = (int)(lin & 4095);
        float s = __ldg(scales + o * GROUPS + (k >> 7));
        __half2 h0 = __floats2half2_rn((float)q.x * s, (float)q.y * s);
        __half2 h1 = __floats2half2_rn((float)q.z * s, (float)q.w * s);
        uint2 u;
        u.x = *reinterpret_cast<uint32_t*>(&h0);
        u.y = *reinterpret_cast<uint32_t*>(&h1);
        reinterpret_cast<uint2*>(g_Wh)[i] = u;
    }
}

// ---------------------------------------------------------------------------
// Helpers
// ---------------------------------------------------------------------------
__device__ __forceinline__ uint32_t smem_u32(const void* p) {
    uint32_t a;
    asm("{ .reg .u64 t; cvta.to.shared.u64 t, %1; cvt.u32.u64 %0, t; }"
        : "=r"(a) : "l"(p));
    return a;
}

__device__ __forceinline__ uint32_t sw128(uint32_t o) {
    return o ^ ((o >> 3) & 0x70);
}

__device__ __forceinline__ void ldsm_x4(uint32_t* r, uint32_t addr) {
    asm volatile("ldmatrix.sync.aligned.m8n8.x4.shared.b16 {%0,%1,%2,%3}, [%4];"
                 : "=r"(r[0]), "=r"(r[1]), "=r"(r[2]), "=r"(r[3])
                 : "r"(addr));
}

__device__ __forceinline__ void mma16816(float* c, const uint32_t* a,
                                         const uint32_t* b) {
    asm volatile(
        "mma.sync.aligned.m16n8k16.row.col.f32.f16.f16.f32 "
        "{%0,%1,%2,%3}, {%4,%5,%6,%7}, {%8,%9}, {%0,%1,%2,%3};"
        : "+f"(c[0]), "+f"(c[1]), "+f"(c[2]), "+f"(c[3])
        : "r"(a[0]), "r"(a[1]), "r"(a[2]), "r"(a[3]), "r"(b[0]), "r"(b[1]));
}

// ---------------------------------------------------------------------------
// GEMM: C[8192,4096] = Xh @ Wh^T + bias
// BM=128, BN=128, BK=64, 3 stages, 256 threads (8 warps, 2x4), warp tile
// 64x32, 2 CTAs/SM. R10 structure (prefetch before compute) + R11's
// algebraically collapsed loader (the reorder from R11 is reverted).
// ---------------------------------------------------------------------------
static constexpr int BM = 128;
static constexpr int BN = 128;
static constexpr int BK = 64;                 // halves; 128 bytes per row
static constexpr int STAGES = 3;
static constexpr int KITERS = INDIM / BK;     // 64
static constexpr int A_BYTES = BM * 128;      // 16384
static constexpr int STAGE_BYTES = A_BYTES + BN * 128;  // 32768
static constexpr int SMEM_BYTES = STAGES * STAGE_BYTES + 1024;  // 99328

__global__ void __launch_bounds__(256, 2)
gemm_kernel(float* __restrict__ out, const float* __restrict__ bias) {
    extern __shared__ char smem[];
    const uint32_t sb = (smem_u32(smem) + 1023u) & ~1023u;
    const int tid  = threadIdx.x;
    const int lane = tid & 31;
    const int wid  = tid >> 5;
    const int wm   = wid >> 2;    // 0..1 (64 rows each)
    const int wn   = wid & 3;     // 0..3 (32 cols each)
    const int n0   = blockIdx.x * BN;
    const int m0   = blockIdx.y * BM;

    // --- Loader bases (j-invariant algebra):
    // chunk c = tid + j*256  ->  row = (tid>>3) + 32j, chunk-in-row = tid&7.
    // 32j = 0 mod 8  =>  swizzle XOR is j-invariant: soff(j) = soff0 + j*4096.
    const int base_r = tid >> 3;
    const uint32_t so0 = sw128((uint32_t)(base_r * 128 + (tid & 7) * 16));
    const __half* gA = g_Xh + (size_t)(m0 + base_r) * INDIM + (tid & 7) * 8;
    const __half* gB = g_Wh + (size_t)(n0 + base_r) * INDIM + (tid & 7) * 8;
    static constexpr size_t RSTRIDE = (size_t)32 * INDIM;   // 32 rows

    auto load_stage = [&](int s, int kiter) {
        const uint32_t st = sb + s * STAGE_BYTES;
        const int k0 = kiter * BK;
        #pragma unroll
        for (int j = 0; j < 4; j++)
            asm volatile("cp.async.cg.shared.global [%0], [%1], 16;"
                         :: "r"(st + so0 + j * 4096),
                            "l"(gA + j * RSTRIDE + k0) : "memory");
        #pragma unroll
        for (int j = 0; j < 4; j++)
            asm volatile("cp.async.cg.shared.global [%0], [%1], 16;"
                         :: "r"(st + A_BYTES + so0 + j * 4096),
                            "l"(gB + j * RSTRIDE + k0) : "memory");
        asm volatile("cp.async.commit_group;" ::: "memory");
    };

    // Per-thread ldmatrix address components
    const int a_row = lane & 15;                       // 0..15
    const int a_col = (lane >> 4) << 4;                // 0 or 16 bytes
    const uint32_t a_xor = (uint32_t)((a_row & 7) << 4);
    const int b_row = ((lane >> 4) << 3) | (lane & 7); // 0..15
    const int b_col = ((lane >> 3) & 1) << 4;          // 0 or 16 bytes
    const uint32_t b_xor = (uint32_t)((b_row & 7) << 4);

    float acc[4][4][4];   // [m16 tile][n8 tile][frag]
    #pragma unroll
    for (int mt = 0; mt < 4; mt++)
        #pragma unroll
        for (int n = 0; n < 4; n++)
            #pragma unroll
            for (int j = 0; j < 4; j++) acc[mt][n][j] = 0.0f;

    // Prologue: 2 stages in flight
    load_stage(0, 0);
    load_stage(1, 1);

    int s = 0;
    for (int i = 0; i < KITERS; i++) {
        asm volatile("cp.async.wait_group 1;" ::: "memory");
        __syncthreads();

        // Prefetch stage i+2 (buffer freed by the barrier above)
        if (i + 2 < KITERS) {
            load_stage(s == 0 ? 2 : s - 1, i + 2);   // (i+2)%3
        } else {
            asm volatile("cp.async.commit_group;" ::: "memory");
        }

        // Compute on stage s
        const uint32_t stg = sb + s * STAGE_BYTES;
        const uint32_t aT = stg + (uint32_t)((wm * 64 + a_row) * 128);
        const uint32_t bT = stg + A_BYTES + (uint32_t)((wn * 32 + b_row) * 128);

        #pragma unroll
        for (int ks = 0; ks < 4; ks++) {
            uint32_t af[4][4], bf[2][4];
            #pragma unroll
            for (int mt = 0; mt < 4; mt++)
                ldsm_x4(af[mt], aT + (uint32_t)(mt * 16 * 128)
                                   + (((uint32_t)(ks * 32 + a_col)) ^ a_xor));
            #pragma unroll
            for (int nt = 0; nt < 2; nt++)
                ldsm_x4(bf[nt], bT + (uint32_t)(nt * 16 * 128)
                                   + (((uint32_t)(ks * 32 + b_col)) ^ b_xor));
            #pragma unroll
            for (int mt = 0; mt < 4; mt++)
                #pragma unroll
                for (int nt = 0; nt < 2; nt++) {
                    mma16816(acc[mt][2 * nt],     af[mt], &bf[nt][0]);
                    mma16816(acc[mt][2 * nt + 1], af[mt], &bf[nt][2]);
                }
        }
        s = (s == STAGES - 1) ? 0 : s + 1;
    }

    // Epilogue: direct fp32 stores with bias
    const int qr = lane >> 2, qc = lane & 3;
    float bv[4][2];
    #pragma unroll
    for (int n = 0; n < 4; n++) {
        const int col = n0 + wn * 32 + n * 8 + qc * 2;
        bv[n][0] = __ldg(bias + col);
        bv[n][1] = __ldg(bias + col + 1);
    }
    #pragma unroll
    for (int mt = 0; mt < 4; mt++) {
        #pragma unroll
        for (int h = 0; h < 2; h++) {
            const int row = m0 + wm * 64 + mt * 16 + qr + h * 8;
            float* orow = out + (size_t)row * OUTDIM + n0 + wn * 32;
            #pragma unroll
            for (int n = 0; n < 4; n++) {
                float2 v;
                v.x = acc[mt][n][2 * h]     + bv[n][0];
                v.y = acc[mt][n][2 * h + 1] + bv[n][1];
                *reinterpret_cast<float2*>(orow + n * 8 + qc * 2) = v;
            }
        }
    }
}

// ---------------------------------------------------------------------------
// Harness entry
// ---------------------------------------------------------------------------
extern "C" void kernel_launch(void* const* d_in, const int* in_sizes, int n_in,
                              void* d_out, int out_size) {
    const float* x      = (const float*)d_in[0];
    const int*   Qw     = (const int*)d_in[1];
    const float* scales = (const float*)d_in[2];
    const float* bias   = (const float*)d_in[3];
    float*       out    = (float*)d_out;

    prep_kernel<<<XBLK + WBLK, 256>>>(x, Qw, scales);

    cudaFuncSetAttribute(gemm_kernel,
                         cudaFuncAttributeMaxDynamicSharedMemorySize, SMEM_BYTES);
    gemm_kernel<<<dim3(OUTDIM / BN, TOKENS / BM), 256, SMEM_BYTES>>>(out, bias);
}

// round 13
// speedup vs baseline: 1.1171x; 1.0740x over previous
#include <cuda_runtime.h>
#include <cuda_fp16.h>
#include <cstdint>
#include <cstddef>

// Problem sizes (fixed by the dataset)
static constexpr int TOKENS = 8192;
static constexpr int INDIM  = 4096;
static constexpr int OUTDIM = 4096;
static constexpr int GROUPS = 32;      // INDIM / 128

// fp16 staging buffers (static device allocs are allowed; cudaMalloc is not)
__device__ __half g_Xh[(size_t)TOKENS * INDIM];   // 64 MB
__device__ __half g_Wh[(size_t)OUTDIM * INDIM];   // 32 MB

// ---------------------------------------------------------------------------
// Fused prologue: blocks [0, XBLK) convert x -> fp16; the rest dequantize W.
// ---------------------------------------------------------------------------
static constexpr int XBLK = (TOKENS * (INDIM / 4)) / 256;    // 32768
static constexpr int WBLK = (OUTDIM * (INDIM / 4)) / 256;    // 16384

__global__ void __launch_bounds__(256)
prep_kernel(const float* __restrict__ x, const int* __restrict__ Q,
            const float* __restrict__ scales) {
    if (blockIdx.x < XBLK) {
        size_t i = (size_t)blockIdx.x * 256 + threadIdx.x;     // float4 index
        float4 v = reinterpret_cast<const float4*>(x)[i];
        __half2 h0 = __floats2half2_rn(v.x, v.y);
        __half2 h1 = __floats2half2_rn(v.z, v.w);
        uint2 u;
        u.x = *reinterpret_cast<uint32_t*>(&h0);
        u.y = *reinterpret_cast<uint32_t*>(&h1);
        reinterpret_cast<uint2*>(g_Xh)[i] = u;
    } else {
        size_t i = (size_t)(blockIdx.x - XBLK) * 256 + threadIdx.x;  // int4 idx
        int4 q = reinterpret_cast<const int4*>(Q)[i];
        size_t lin = i * 4;
        int o = (int)(lin >> 12);            // / 4096
        int k = (int)(lin & 4095);
        float s = __ldg(scales + o * GROUPS + (k >> 7));
        __half2 h0 = __floats2half2_rn((float)q.x * s, (float)q.y * s);
        __half2 h1 = __floats2half2_rn((float)q.z * s, (float)q.w * s);
        uint2 u;
        u.x = *reinterpret_cast<uint32_t*>(&h0);
        u.y = *reinterpret_cast<uint32_t*>(&h1);
        reinterpret_cast<uint2*>(g_Wh)[i] = u;
    }
}

// ---------------------------------------------------------------------------
// Helpers
// ---------------------------------------------------------------------------
__device__ __forceinline__ uint32_t smem_u32(const void* p) {
    uint32_t a;
    asm("{ .reg .u64 t; cvta.to.shared.u64 t, %1; cvt.u32.u64 %0, t; }"
        : "=r"(a) : "l"(p));
    return a;
}

__device__ __forceinline__ uint32_t sw128(uint32_t o) {
    return o ^ ((o >> 3) & 0x70);
}

__device__ __forceinline__ void ldsm_x4(uint32_t* r, uint32_t addr) {
    asm volatile("ldmatrix.sync.aligned.m8n8.x4.shared.b16 {%0,%1,%2,%3}, [%4];"
                 : "=r"(r[0]), "=r"(r[1]), "=r"(r[2]), "=r"(r[3])
                 : "r"(addr));
}

__device__ __forceinline__ void mma16816(float* c, const uint32_t* a,
                                         const uint32_t* b) {
    asm volatile(
        "mma.sync.aligned.m16n8k16.row.col.f32.f16.f16.f32 "
        "{%0,%1,%2,%3}, {%4,%5,%6,%7}, {%8,%9}, {%0,%1,%2,%3};"
        : "+f"(c[0]), "+f"(c[1]), "+f"(c[2]), "+f"(c[3])
        : "r"(a[0]), "r"(a[1]), "r"(a[2]), "r"(a[3]), "r"(b[0]), "r"(b[1]));
}

// mbarrier primitives (all sm_80/sm_90 baseline PTX -> compile for sm_100)
__device__ __forceinline__ void mbar_init(uint32_t a, uint32_t n) {
    asm volatile("mbarrier.init.shared.b64 [%0], %1;" :: "r"(a), "r"(n)
                 : "memory");
}
__device__ __forceinline__ void mbar_arrive(uint32_t a) {
    asm volatile("{ .reg .b64 t; mbarrier.arrive.shared.b64 t, [%0]; }"
                 :: "r"(a) : "memory");
}
__device__ __forceinline__ void mbar_wait(uint32_t a, uint32_t ph) {
    asm volatile(
        "{\n\t.reg .pred P;\n\t"
        "W%=:\n\t"
        "mbarrier.try_wait.parity.shared.b64 P, [%0], %1;\n\t"
        "@P bra D%=;\n\t"
        "bra W%=;\n\t"
        "D%=:\n\t}"
        :: "r"(a), "r"(ph) : "memory");
}
__device__ __forceinline__ void cpasync_arrive_noinc(uint32_t a) {
    asm volatile("cp.async.mbarrier.arrive.noinc.shared.b64 [%0];"
                 :: "r"(a) : "memory");
}

// ---------------------------------------------------------------------------
// GEMM: C[8192,4096] = Xh @ Wh^T + bias
// BM=128, BN=128, BK=64, 3-stage mbarrier full/empty ring (no __syncthreads
// in the mainloop -> warps decouple; convergence jitter absorbed by ring).
// 256 threads (8 warps, 2x4), warp tile 64x32, 2 CTAs/SM.
// ---------------------------------------------------------------------------
static constexpr int BM = 128;
static constexpr int BN = 128;
static constexpr int BK = 64;                 // halves; 128 bytes per row
static constexpr int STAGES = 3;
static constexpr int KITERS = INDIM / BK;     // 64
static constexpr int A_BYTES = BM * 128;      // 16384
static constexpr int STAGE_BYTES = A_BYTES + BN * 128;  // 32768
// layout: [0,48) mbarriers (full/empty x3), stages at +1024 (1024-aligned)
static constexpr int SMEM_BYTES = 1024 + STAGES * STAGE_BYTES + 1024; // 100352

__global__ void __launch_bounds__(256, 2)
gemm_kernel(float* __restrict__ out, const float* __restrict__ bias) {
    extern __shared__ char smem[];
    const uint32_t sbH = (smem_u32(smem) + 1023u) & ~1023u;  // barrier block
    const uint32_t sb  = sbH + 1024;                          // stage data
    const int tid  = threadIdx.x;
    const int lane = tid & 31;
    const int wid  = tid >> 5;
    const int wm   = wid >> 2;    // 0..1 (64 rows each)
    const int wn   = wid & 3;     // 0..3 (32 cols each)
    const int n0   = blockIdx.x * BN;
    const int m0   = blockIdx.y * BM;

    // full[s] = sbH + s*16, empty[s] = sbH + s*16 + 8
    if (tid == 0) {
        #pragma unroll
        for (int s = 0; s < STAGES; s++) {
            mbar_init(sbH + s * 16, 256u);     // full: one arrive per thread
            mbar_init(sbH + s * 16 + 8, 8u);   // empty: one arrive per warp
        }
    }
    __syncthreads();   // init visible before any arrive/wait

    // Loader bases (j-invariant algebra, proven in R11/R12)
    const int base_r = tid >> 3;
    const uint32_t so0 = sw128((uint32_t)(base_r * 128 + (tid & 7) * 16));
    const __half* gA = g_Xh + (size_t)(m0 + base_r) * INDIM + (tid & 7) * 8;
    const __half* gB = g_Wh + (size_t)(n0 + base_r) * INDIM + (tid & 7) * 8;
    static constexpr size_t RSTRIDE = (size_t)32 * INDIM;   // 32 rows

    auto fill_stage = [&](int s, int kiter) {
        const uint32_t st = sb + s * STAGE_BYTES;
        const int k0 = kiter * BK;
        #pragma unroll
        for (int j = 0; j < 4; j++)
            asm volatile("cp.async.cg.shared.global [%0], [%1], 16;"
                         :: "r"(st + so0 + j * 4096),
                            "l"(gA + j * RSTRIDE + k0) : "memory");
        #pragma unroll
        for (int j = 0; j < 4; j++)
            asm volatile("cp.async.cg.shared.global [%0], [%1], 16;"
                         :: "r"(st + A_BYTES + so0 + j * 4096),
                            "l"(gB + j * RSTRIDE + k0) : "memory");
        cpasync_arrive_noinc(sbH + s * 16);    // full[s] when copies land
    };

    // Per-thread ldmatrix address components
    const int a_row = lane & 15;                       // 0..15
    const int a_col = (lane >> 4) << 4;                // 0 or 16 bytes
    const uint32_t a_xor = (uint32_t)((a_row & 7) << 4);
    const int b_row = ((lane >> 4) << 3) | (lane & 7); // 0..15
    const int b_col = ((lane >> 3) & 1) << 4;          // 0 or 16 bytes
    const uint32_t b_xor = (uint32_t)((b_row & 7) << 4);

    float acc[4][4][4];   // [m16 tile][n8 tile][frag]
    #pragma unroll
    for (int mt = 0; mt < 4; mt++)
        #pragma unroll
        for (int n = 0; n < 4; n++)
            #pragma unroll
            for (int j = 0; j < 4; j++) acc[mt][n][j] = 0.0f;

    // Cursors: consumer (stage 0, phase 0); producer (stage 0, phase 1)
    int cs = 0, cph = 0;
    int ps = 0, pph = 1;

    // Prologue: fill stages 0,1 (empty-wait passes on fresh barriers @ parity 1)
    #pragma unroll
    for (int t = 0; t < 2; t++) {
        mbar_wait(sbH + ps * 16 + 8, (uint32_t)pph);
        fill_stage(ps, t);
        if (++ps == STAGES) { ps = 0; pph ^= 1; }
    }

    for (int i = 0; i < KITERS; i++) {
        // Consume stage cs (kiter i)
        mbar_wait(sbH + cs * 16, (uint32_t)cph);

        const uint32_t stg = sb + cs * STAGE_BYTES;
        const uint32_t aT = stg + (uint32_t)((wm * 64 + a_row) * 128);
        const uint32_t bT = stg + A_BYTES + (uint32_t)((wn * 32 + b_row) * 128);

        #pragma unroll
        for (int ks = 0; ks < 4; ks++) {
            uint32_t af[4][4], bf[2][4];
            #pragma unroll
            for (int mt = 0; mt < 4; mt++)
                ldsm_x4(af[mt], aT + (uint32_t)(mt * 16 * 128)
                                   + (((uint32_t)(ks * 32 + a_col)) ^ a_xor));
            #pragma unroll
            for (int nt = 0; nt < 2; nt++)
                ldsm_x4(bf[nt], bT + (uint32_t)(nt * 16 * 128)
                                   + (((uint32_t)(ks * 32 + b_col)) ^ b_xor));
            #pragma unroll
            for (int mt = 0; mt < 4; mt++)
                #pragma unroll
                for (int nt = 0; nt < 2; nt++) {
                    mma16816(acc[mt][2 * nt],     af[mt], &bf[nt][0]);
                    mma16816(acc[mt][2 * nt + 1], af[mt], &bf[nt][2]);
                }
        }

        // Warp finished reading stage cs -> release it
        __syncwarp();
        if (lane == 0) mbar_arrive(sbH + cs * 16 + 8);
        if (++cs == STAGES) { cs = 0; cph ^= 1; }

        // Refill stage (i+2)%3 with kiter i+2
        if (i + 2 < KITERS) {
            mbar_wait(sbH + ps * 16 + 8, (uint32_t)pph);
            fill_stage(ps, i + 2);
            if (++ps == STAGES) { ps = 0; pph ^= 1; }
        }
    }

    // Epilogue: direct fp32 stores with bias (regs only; no smem dependence)
    const int qr = lane >> 2, qc = lane & 3;
    float bv[4][2];
    #pragma unroll
    for (int n = 0; n < 4; n++) {
        const int col = n0 + wn * 32 + n * 8 + qc * 2;
        bv[n][0] = __ldg(bias + col);
        bv[n][1] = __ldg(bias + col + 1);
    }
    #pragma unroll
    for (int mt = 0; mt < 4; mt++) {
        #pragma unroll
        for (int h = 0; h < 2; h++) {
            const int row = m0 + wm * 64 + mt * 16 + qr + h * 8;
            float* orow = out + (size_t)row * OUTDIM + n0 + wn * 32;
            #pragma unroll
            for (int n = 0; n < 4; n++) {
                float2 v;
                v.x = acc[mt][n][2 * h]     + bv[n][0];
                v.y = acc[mt][n][2 * h + 1] + bv[n][1];
                *reinterpret_cast<float2*>(orow + n * 8 + qc * 2) = v;
            }
        }
    }
}

// ---------------------------------------------------------------------------
// Harness entry
// ---------------------------------------------------------------------------
extern "C" void kernel_launch(void* const* d_in, const int* in_sizes, int n_in,
                              void* d_out, int out_size) {
    const float* x      = (const float*)d_in[0];
    const int*   Qw     = (const int*)d_in[1];
    const float* scales = (const float*)d_in[2];
    const float* bias   = (const float*)d_in[3];
    float*       out    = (float*)d_out;

    prep_kernel<<<XBLK + WBLK, 256>>>(x, Qw, scales);

    cudaFuncSetAttribute(gemm_kernel,
                         cudaFuncAttributeMaxDynamicSharedMemorySize, SMEM_BYTES);
    gemm_kernel<<<dim3(OUTDIM / BN, TOKENS / BM), 256, SMEM_BYTES>>>(out, bias);
}

// round 16
// speedup vs baseline: 1.1200x; 1.0026x over previous
#include <cuda_runtime.h>
#include <cuda_fp16.h>
#include <cstdint>
#include <cstddef>

// Problem sizes (fixed by the dataset)
static constexpr int TOKENS = 8192;
static constexpr int INDIM  = 4096;
static constexpr int OUTDIM = 4096;
static constexpr int GROUPS = 32;      // INDIM / 128

// fp16 staging buffers (static device allocs are allowed; cudaMalloc is not)
__device__ __half g_Xh[(size_t)TOKENS * INDIM];   // 64 MB
__device__ __half g_Wh[(size_t)OUTDIM * INDIM];   // 32 MB

// ---------------------------------------------------------------------------
// Fused prologue: blocks [0, XBLK) convert x -> fp16; the rest dequantize W.
// ---------------------------------------------------------------------------
static constexpr int XBLK = (TOKENS * (INDIM / 4)) / 256;    // 32768
static constexpr int WBLK = (OUTDIM * (INDIM / 4)) / 256;    // 16384

__global__ void __launch_bounds__(256)
prep_kernel(const float* __restrict__ x, const int* __restrict__ Q,
            const float* __restrict__ scales) {
    if (blockIdx.x < XBLK) {
        size_t i = (size_t)blockIdx.x * 256 + threadIdx.x;     // float4 index
        float4 v = reinterpret_cast<const float4*>(x)[i];
        __half2 h0 = __floats2half2_rn(v.x, v.y);
        __half2 h1 = __floats2half2_rn(v.z, v.w);
        uint2 u;
        u.x = *reinterpret_cast<uint32_t*>(&h0);
        u.y = *reinterpret_cast<uint32_t*>(&h1);
        reinterpret_cast<uint2*>(g_Xh)[i] = u;
    } else {
        size_t i = (size_t)(blockIdx.x - XBLK) * 256 + threadIdx.x;  // int4 idx
        int4 q = reinterpret_cast<const int4*>(Q)[i];
        size_t lin = i * 4;
        int o = (int)(lin >> 12);            // / 4096
        int k = (int)(lin & 4095);
        float s = __ldg(scales + o * GROUPS + (k >> 7));
        __half2 h0 = __floats2half2_rn((float)q.x * s, (float)q.y * s);
        __half2 h1 = __floats2half2_rn((float)q.z * s, (float)q.w * s);
        uint2 u;
        u.x = *reinterpret_cast<uint32_t*>(&h0);
        u.y = *reinterpret_cast<uint32_t*>(&h1);
        reinterpret_cast<uint2*>(g_Wh)[i] = u;
    }
}

// ---------------------------------------------------------------------------
// Helpers
// ---------------------------------------------------------------------------
__device__ __forceinline__ uint32_t smem_u32(const void* p) {
    uint32_t a;
    asm("{ .reg .u64 t; cvta.to.shared.u64 t, %1; cvt.u32.u64 %0, t; }"
        : "=r"(a) : "l"(p));
    return a;
}

__device__ __forceinline__ uint32_t sw128(uint32_t o) {
    return o ^ ((o >> 3) & 0x70);
}

__device__ __forceinline__ void ldsm_x4(uint32_t* r, uint32_t addr) {
    asm volatile("ldmatrix.sync.aligned.m8n8.x4.shared.b16 {%0,%1,%2,%3}, [%4];"
                 : "=r"(r[0]), "=r"(r[1]), "=r"(r[2]), "=r"(r[3])
                 : "r"(addr));
}

__device__ __forceinline__ void mma16816(float* c, const uint32_t* a,
                                         const uint32_t* b) {
    asm volatile(
        "mma.sync.aligned.m16n8k16.row.col.f32.f16.f16.f32 "
        "{%0,%1,%2,%3}, {%4,%5,%6,%7}, {%8,%9}, {%0,%1,%2,%3};"
        : "+f"(c[0]), "+f"(c[1]), "+f"(c[2]), "+f"(c[3])
        : "r"(a[0]), "r"(a[1]), "r"(a[2]), "r"(a[3]), "r"(b[0]), "r"(b[1]));
}

// mbarrier primitives (all sm_80/sm_90 baseline PTX -> compile for sm_100)
__device__ __forceinline__ void mbar_init(uint32_t a, uint32_t n) {
    asm volatile("mbarrier.init.shared.b64 [%0], %1;" :: "r"(a), "r"(n)
                 : "memory");
}
__device__ __forceinline__ void mbar_arrive(uint32_t a) {
    asm volatile("{ .reg .b64 t; mbarrier.arrive.shared.b64 t, [%0]; }"
                 :: "r"(a) : "memory");
}
__device__ __forceinline__ void mbar_wait(uint32_t a, uint32_t ph) {
    asm volatile(
        "{\n\t.reg .pred P;\n\t"
        "W%=:\n\t"
        "mbarrier.try_wait.parity.shared.b64 P, [%0], %1;\n\t"
        "@P bra D%=;\n\t"
        "bra W%=;\n\t"
        "D%=:\n\t}"
        :: "r"(a), "r"(ph) : "memory");
}
__device__ __forceinline__ void cpasync_arrive_noinc(uint32_t a) {
    asm volatile("cp.async.mbarrier.arrive.noinc.shared.b64 [%0];"
                 :: "r"(a) : "memory");
}

// ---------------------------------------------------------------------------
// GEMM: C[8192,4096] = Xh @ Wh^T + bias
// BM=128, BN=128, BK=64, 3-stage mbarrier full/empty ring. R13 structure +
// EARLY RELEASE: empty[cs] arrive moves to right after the last ldsm of the
// stage (release-ordering of the arrive covers the reads; producer data
// cannot land before its >=250cyc global fetch). Producer lead lengthens by
// ~16 MMA latencies per iteration; slowest-warp release happens earlier.
// ---------------------------------------------------------------------------
static constexpr int BM = 128;
static constexpr int BN = 128;
static constexpr int BK = 64;                 // halves; 128 bytes per row
static constexpr int STAGES = 3;
static constexpr int KITERS = INDIM / BK;     // 64
static constexpr int A_BYTES = BM * 128;      // 16384
static constexpr int STAGE_BYTES = A_BYTES + BN * 128;  // 32768
static constexpr int SMEM_BYTES = 1024 + STAGES * STAGE_BYTES + 1024; // 100352

__global__ void __launch_bounds__(256, 2)
gemm_kernel(float* __restrict__ out, const float* __restrict__ bias) {
    extern __shared__ char smem[];
    const uint32_t sbH = (smem_u32(smem) + 1023u) & ~1023u;  // barrier block
    const uint32_t sb  = sbH + 1024;                          // stage data
    const int tid  = threadIdx.x;
    const int lane = tid & 31;
    const int wid  = tid >> 5;
    const int wm   = wid >> 2;    // 0..1 (64 rows each)
    const int wn   = wid & 3;     // 0..3 (32 cols each)
    const int n0   = blockIdx.x * BN;
    const int m0   = blockIdx.y * BM;

    // full[s] = sbH + s*16, empty[s] = sbH + s*16 + 8
    if (tid == 0) {
        #pragma unroll
        for (int s = 0; s < STAGES; s++) {
            mbar_init(sbH + s * 16, 256u);     // full: one arrive per thread
            mbar_init(sbH + s * 16 + 8, 8u);   // empty: one arrive per warp
        }
    }
    __syncthreads();   // init visible before any arrive/wait

    // Loader bases (j-invariant algebra, proven in R11/R12)
    const int base_r = tid >> 3;
    const uint32_t so0 = sw128((uint32_t)(base_r * 128 + (tid & 7) * 16));
    const __half* gA = g_Xh + (size_t)(m0 + base_r) * INDIM + (tid & 7) * 8;
    const __half* gB = g_Wh + (size_t)(n0 + base_r) * INDIM + (tid & 7) * 8;
    static constexpr size_t RSTRIDE = (size_t)32 * INDIM;   // 32 rows

    auto fill_stage = [&](int s, int kiter) {
        const uint32_t st = sb + s * STAGE_BYTES;
        const int k0 = kiter * BK;
        #pragma unroll
        for (int j = 0; j < 4; j++)
            asm volatile("cp.async.cg.shared.global [%0], [%1], 16;"
                         :: "r"(st + so0 + j * 4096),
                            "l"(gA + j * RSTRIDE + k0) : "memory");
        #pragma unroll
        for (int j = 0; j < 4; j++)
            asm volatile("cp.async.cg.shared.global [%0], [%1], 16;"
                         :: "r"(st + A_BYTES + so0 + j * 4096),
                            "l"(gB + j * RSTRIDE + k0) : "memory");
        cpasync_arrive_noinc(sbH + s * 16);    // full[s] when copies land
    };

    // Per-thread ldmatrix address components
    const int a_row = lane & 15;                       // 0..15
    const int a_col = (lane >> 4) << 4;                // 0 or 16 bytes
    const uint32_t a_xor = (uint32_t)((a_row & 7) << 4);
    const int b_row = ((lane >> 4) << 3) | (lane & 7); // 0..15
    const int b_col = ((lane >> 3) & 1) << 4;          // 0 or 16 bytes
    const uint32_t b_xor = (uint32_t)((b_row & 7) << 4);

    float acc[4][4][4];   // [m16 tile][n8 tile][frag]
    #pragma unroll
    for (int mt = 0; mt < 4; mt++)
        #pragma unroll
        for (int n = 0; n < 4; n++)
            #pragma unroll
            for (int j = 0; j < 4; j++) acc[mt][n][j] = 0.0f;

    // Cursors: consumer (stage 0, phase 0); producer (stage 0, phase 1)
    int cs = 0, cph = 0;
    int ps = 0, pph = 1;

    // Prologue: fill stages 0,1 (empty-wait passes on fresh barriers @ parity 1)
    #pragma unroll
    for (int t = 0; t < 2; t++) {
        mbar_wait(sbH + ps * 16 + 8, (uint32_t)pph);
        fill_stage(ps, t);
        if (++ps == STAGES) { ps = 0; pph ^= 1; }
    }

    for (int i = 0; i < KITERS; i++) {
        // Consume stage cs (kiter i)
        mbar_wait(sbH + cs * 16, (uint32_t)cph);

        const uint32_t stg = sb + cs * STAGE_BYTES;
        const uint32_t aT = stg + (uint32_t)((wm * 64 + a_row) * 128);
        const uint32_t bT = stg + A_BYTES + (uint32_t)((wn * 32 + b_row) * 128);

        #pragma unroll
        for (int ks = 0; ks < 4; ks++) {
            uint32_t af[4][4], bf[2][4];
            #pragma unroll
            for (int mt = 0; mt < 4; mt++)
                ldsm_x4(af[mt], aT + (uint32_t)(mt * 16 * 128)
                                   + (((uint32_t)(ks * 32 + a_col)) ^ a_xor));
            #pragma unroll
            for (int nt = 0; nt < 2; nt++)
                ldsm_x4(bf[nt], bT + (uint32_t)(nt * 16 * 128)
                                   + (((uint32_t)(ks * 32 + b_col)) ^ b_xor));

            // EARLY RELEASE: last smem read of this stage just issued; the
            // release-ordered arrive frees the stage before the ks=3 MMAs.
            if (ks == 3 && lane == 0) mbar_arrive(sbH + cs * 16 + 8);

            #pragma unroll
            for (int mt = 0; mt < 4; mt++)
                #pragma unroll
                for (int nt = 0; nt < 2; nt++) {
                    mma16816(acc[mt][2 * nt],     af[mt], &bf[nt][0]);
                    mma16816(acc[mt][2 * nt + 1], af[mt], &bf[nt][2]);
                }
        }
        if (++cs == STAGES) { cs = 0; cph ^= 1; }

        // Refill stage (i+2)%3 with kiter i+2
        if (i + 2 < KITERS) {
            mbar_wait(sbH + ps * 16 + 8, (uint32_t)pph);
            fill_stage(ps, i + 2);
            if (++ps == STAGES) { ps = 0; pph ^= 1; }
        }
    }

    // Epilogue: direct fp32 stores with bias (regs only; no smem dependence)
    const int qr = lane >> 2, qc = lane & 3;
    float bv[4][2];
    #pragma unroll
    for (int n = 0; n < 4; n++) {
        const int col = n0 + wn * 32 + n * 8 + qc * 2;
        bv[n][0] = __ldg(bias + col);
        bv[n][1] = __ldg(bias + col + 1);
    }
    #pragma unroll
    for (int mt = 0; mt < 4; mt++) {
        #pragma unroll
        for (int h = 0; h < 2; h++) {
            const int row = m0 + wm * 64 + mt * 16 + qr + h * 8;
            float* orow = out + (size_t)row * OUTDIM + n0 + wn * 32;
            #pragma unroll
            for (int n = 0; n < 4; n++) {
                float2 v;
                v.x = acc[mt][n][2 * h]     + bv[n][0];
                v.y = acc[mt][n][2 * h + 1] + bv[n][1];
                *reinterpret_cast<float2*>(orow + n * 8 + qc * 2) = v;
            }
        }
    }
}

// ---------------------------------------------------------------------------
// Harness entry
// ---------------------------------------------------------------------------
extern "C" void kernel_launch(void* const* d_in, const int* in_sizes, int n_in,
                              void* d_out, int out_size) {
    const float* x      = (const float*)d_in[0];
    const int*   Qw     = (const int*)d_in[1];
    const float* scales = (const float*)d_in[2];
    const float* bias   = (const float*)d_in[3];
    float*       out    = (float*)d_out;

    prep_kernel<<<XBLK + WBLK, 256>>>(x, Qw, scales);

    cudaFuncSetAttribute(gemm_kernel,
                         cudaFuncAttributeMaxDynamicSharedMemorySize, SMEM_BYTES);
    gemm_kernel<<<dim3(OUTDIM / BN, TOKENS / BM), 256, SMEM_BYTES>>>(out, bias);
}